// round 16
// baseline (speedup 1.0000x reference)
#include <cuda_runtime.h>
#include <cuda_bf16.h>
#include <cuda_fp16.h>

#define NN 50000
#define NE 600000
#define LAT 128
#define NF 7
#define TILES 391          // ceil(NN/128)
#define NPERS 262          // persistent grid, 2 CTAs/SM
#define PA 136             // fp16 elems per image row (272B: conflict-free ldmatrix)
#define IMG_BYTES (128 * PA * 2)   // 34816

// smem layout (bytes): A + W1 + W2 (single fp16) + bias
#define SM_A    0
#define SM_W1   (SM_A + IMG_BYTES)
#define SM_W2   (SM_W1 + IMG_BYTES)
#define SM_BIAS (SM_W2 + IMG_BYTES)        // 104448
#define SM_TOTAL (SM_BIAS + 1024)          // 105472 (x2 CTAs fits)

// ---------------- scratch ----------------
__device__ float  g_h[NN * LAT];
__device__ __half g_xA[NN * LAT];          // ping
__device__ __half g_xB[NN * LAT];          // pong
__device__ float  g_degs[NN];              // zero-initialized; re-zeroed by place_kernel
__device__ float  g_degr[NN];
__device__ float  g_invs[NN];
__device__ float  g_invr[NN];
__device__ int    g_off[NN + 1];
__device__ int    g_cursor[NN];
__device__ int    g_esrc[NE];
__device__ int    g_bsum[64];
__device__ unsigned char g_aimg[(size_t)TILES * IMG_BYTES];   // fp16 A images (step 0 only)
__device__ unsigned char g_wimg[6 * IMG_BYTES];               // fp16 W images

// ---------------- helpers ----------------
__device__ __forceinline__ unsigned smem_u32(const void* p) {
    unsigned a;
    asm("{ .reg .u64 t; cvta.to.shared.u64 t, %1; cvt.u32.u64 %0, t; }"
        : "=r"(a) : "l"(p));
    return a;
}
__device__ __forceinline__ void cpasync16(unsigned s, const void* g) {
    asm volatile("cp.async.cg.shared.global [%0], [%1], 16;" :: "r"(s), "l"(g));
}
__device__ __forceinline__ unsigned pack_h2(float v0, float v1) {
    __half2 h = __halves2half2(__float2half_rn(v0), __float2half_rn(v1));
    return *reinterpret_cast<unsigned*>(&h);
}
__device__ __forceinline__ void store_h_image(int n, int lane, float4 v) {
    int tile = n >> 7, r = n & 127;
    size_t off = (size_t)tile * IMG_BYTES + ((size_t)r * PA + lane * 4) * 2;
    *(uint2*)(g_aimg + off) = make_uint2(pack_h2(v.x, v.y), pack_h2(v.z, v.w));
}
__device__ __forceinline__ void ldsm4(unsigned* r, unsigned addr) {
    asm volatile("ldmatrix.sync.aligned.m8n8.x4.shared.b16 {%0,%1,%2,%3}, [%4];"
                 : "=r"(r[0]), "=r"(r[1]), "=r"(r[2]), "=r"(r[3]) : "r"(addr));
}
__device__ __forceinline__ void ldsm4t(unsigned* r, unsigned addr) {
    asm volatile("ldmatrix.sync.aligned.m8n8.x4.trans.shared.b16 {%0,%1,%2,%3}, [%4];"
                 : "=r"(r[0]), "=r"(r[1]), "=r"(r[2]), "=r"(r[3]) : "r"(addr));
}
__device__ __forceinline__ void mma16816(float* d, const unsigned* a, const unsigned* b) {
    asm volatile(
        "mma.sync.aligned.m16n8k16.row.col.f32.f16.f16.f32 "
        "{%0,%1,%2,%3}, {%4,%5,%6,%7}, {%8,%9}, {%0,%1,%2,%3};"
        : "+f"(d[0]), "+f"(d[1]), "+f"(d[2]), "+f"(d[3])
        : "r"(a[0]), "r"(a[1]), "r"(a[2]), "r"(a[3]), "r"(b[0]), "r"(b[1]));
}

// ---------------- embed + weight images + degree count (degs pre-zeroed) ------
__global__ void embed_deg_kernel(const float* __restrict__ nodes,
                                 const float* __restrict__ We,
                                 const float* __restrict__ be,
                                 const float* __restrict__ mlpW,
                                 const int* __restrict__ snd,
                                 const int* __restrict__ rcv) {
    __shared__ float Wsh[NF * LAT];
    __shared__ float bsh[LAT];
    int tid = threadIdx.x;
    int gid = blockIdx.x * 256 + tid;
    if (gid < NE) {
        atomicAdd(&g_degs[snd[gid]], 1.f);
        atomicAdd(&g_degr[rcv[gid]], 1.f);
    }
    if (gid < 6 * LAT * LAT) {
        int sl = gid >> 14;
        int rem = gid & 16383;
        int k = rem >> 7;
        int j = rem & 127;
        float w = mlpW[(size_t)sl * LAT * LAT + k * LAT + j];
        size_t off = (size_t)sl * IMG_BYTES + ((size_t)k * PA + j) * 2;
        *(__half*)(g_wimg + off) = __float2half_rn(w);
    }
    for (int i = tid; i < NF * LAT; i += 256) Wsh[i] = We[i];
    if (tid < LAT) bsh[tid] = be[tid];
    __syncthreads();
    int warp = tid >> 5, lane = tid & 31;
    int n = blockIdx.x * 8 + warp;
    if (n >= NN) return;
    float t = (lane < NF) ? nodes[n * NF + lane] : 0.f;
    float f[NF];
#pragma unroll
    for (int k = 0; k < NF; k++) f[k] = __shfl_sync(0xFFFFFFFFu, t, k);
    int c0 = lane * 4;
    float4 o = make_float4(bsh[c0], bsh[c0 + 1], bsh[c0 + 2], bsh[c0 + 3]);
#pragma unroll
    for (int k = 0; k < NF; k++) {
        float4 w = *(const float4*)(Wsh + k * LAT + c0);
        o.x = fmaf(f[k], w.x, o.x);
        o.y = fmaf(f[k], w.y, o.y);
        o.z = fmaf(f[k], w.z, o.z);
        o.w = fmaf(f[k], w.w, o.w);
    }
    ((float4*)g_h)[n * 32 + lane] = o;
    store_h_image(n, lane, o);
}

// ---------------- scans ----------------
__global__ void scan1_kernel() {
    int i = blockIdx.x * 1024 + threadIdx.x;
    int v = 0;
    if (i < NN) {
        float ds = g_degs[i], dr = g_degr[i];
        g_invs[i] = rsqrtf(fmaxf(ds, 1.f));
        g_invr[i] = rsqrtf(fmaxf(dr, 1.f));
        v = (int)dr;
    }
#pragma unroll
    for (int o = 16; o; o >>= 1) v += __shfl_xor_sync(0xFFFFFFFFu, v, o);
    __shared__ int ws[32];
    int lane = threadIdx.x & 31, warp = threadIdx.x >> 5;
    if (lane == 0) ws[warp] = v;
    __syncthreads();
    if (warp == 0) {
        int t = ws[lane];
#pragma unroll
        for (int o = 16; o; o >>= 1) t += __shfl_xor_sync(0xFFFFFFFFu, t, o);
        if (lane == 0) g_bsum[blockIdx.x] = t;
    }
}

__global__ void scan3_kernel() {
    __shared__ int part[2];
    __shared__ int ws[32];
    int t = threadIdx.x;
    if (t < 64) {
        int v = (t < (int)blockIdx.x) ? g_bsum[t] : 0;
#pragma unroll
        for (int o = 16; o; o >>= 1) v += __shfl_xor_sync(0xFFFFFFFFu, v, o);
        if ((t & 31) == 0) part[t >> 5] = v;
    }
    __syncthreads();
    int base = part[0] + part[1];

    int i = blockIdx.x * 1024 + t;
    int lane = t & 31, warp = t >> 5;
    int v = (i < NN) ? (int)g_degr[i] : 0;
    int x = v;
#pragma unroll
    for (int o = 1; o < 32; o <<= 1) {
        int y = __shfl_up_sync(0xFFFFFFFFu, x, o);
        if (lane >= o) x += y;
    }
    if (lane == 31) ws[warp] = x;
    __syncthreads();
    if (warp == 0) {
        int tt = ws[lane];
        int xx = tt;
#pragma unroll
        for (int o = 1; o < 32; o <<= 1) {
            int y = __shfl_up_sync(0xFFFFFFFFu, xx, o);
            if (lane >= o) xx += y;
        }
        ws[lane] = xx - tt;
    }
    __syncthreads();
    int ex = x - v + ws[warp] + base;
    if (i < NN) { g_off[i] = ex; g_cursor[i] = ex; }
    if (i == 0) g_off[NN] = NE;
}

// place + re-zero degree arrays for the next call (deterministic invariant)
__global__ void place_kernel(const int* __restrict__ snd, const int* __restrict__ rcv) {
    int e = blockIdx.x * blockDim.x + threadIdx.x;
    if (e < NN) { g_degs[e] = 0.f; g_degr[e] = 0.f; }
    if (e < NE) {
        int pos = atomicAdd(&g_cursor[rcv[e]], 1);
        g_esrc[pos] = snd[e];
    }
}

// ---------------- shared MMA layer (fp16 single-W) ----------------
__device__ __forceinline__ void mma_layer(unsigned sA, unsigned sW,
                                          float acc[2][4][4],
                                          int lane, int row_w, int col_w) {
    int lr = lane & 15, lc = lane >> 4;
    int br = lane & 7, bseg = lane >> 3;
    unsigned a_base = ((row_w + lr) * PA + lc * 8) * 2;
    unsigned b_base = (((bseg & 1) * 8 + br) * PA + col_w + (bseg >> 1) * 8) * 2;

#pragma unroll
    for (int kt = 0; kt < 8; kt++) {
        unsigned a_off = a_base + kt * 32;
        unsigned b_off = b_base + kt * (16 * PA * 2);
        unsigned a[2][4], wh[2][4];
        ldsm4(a[0], sA + a_off);
        ldsm4(a[1], sA + a_off + 16 * PA * 2);
        ldsm4t(wh[0], sW + b_off);
        ldsm4t(wh[1], sW + b_off + 32);
#pragma unroll
        for (int mt = 0; mt < 2; mt++)
#pragma unroll
            for (int nt = 0; nt < 4; nt++)
                mma16816(acc[mt][nt], a[mt], &wh[nt >> 1][(nt & 1) * 2]);
    }
}

// MLP phases (assumes A image + W1/W2 in smem, writes xout fp16)
__device__ __forceinline__ void mlp_tile(unsigned char* smem, unsigned sb, int t,
                                         int tid, int wid, int lane,
                                         __half* __restrict__ xout) {
    int row_w = (wid >> 2) * 32;
    int col_w = (wid & 3) * 32;
    float* b1s = (float*)(smem + SM_BIAS);
    float* b2s = (float*)(smem + SM_BIAS + 512);
    int qr = lane >> 2;
    int qc = (lane & 3) * 2;

    float acc[2][4][4];
#pragma unroll
    for (int mt = 0; mt < 2; mt++)
#pragma unroll
        for (int nt = 0; nt < 4; nt++)
#pragma unroll
            for (int q = 0; q < 4; q++) acc[mt][nt][q] = 0.f;

    mma_layer(sb + SM_A, sb + SM_W1, acc, lane, row_w, col_w);
    __syncthreads();

#pragma unroll
    for (int mt = 0; mt < 2; mt++)
#pragma unroll
        for (int nt = 0; nt < 4; nt++) {
            int r0 = row_w + mt * 16 + qr;
            int c = col_w + nt * 8 + qc;
            float v00 = fmaxf(acc[mt][nt][0] + b1s[c], 0.f);
            float v01 = fmaxf(acc[mt][nt][1] + b1s[c + 1], 0.f);
            float v10 = fmaxf(acc[mt][nt][2] + b1s[c], 0.f);
            float v11 = fmaxf(acc[mt][nt][3] + b1s[c + 1], 0.f);
            *(unsigned*)(smem + SM_A + (r0 * PA + c) * 2) = pack_h2(v00, v01);
            *(unsigned*)(smem + SM_A + ((r0 + 8) * PA + c) * 2) = pack_h2(v10, v11);
#pragma unroll
            for (int q = 0; q < 4; q++) acc[mt][nt][q] = 0.f;
        }
    __syncthreads();

    mma_layer(sb + SM_A, sb + SM_W2, acc, lane, row_w, col_w);
    __syncthreads();  // layer-2 A reads complete before next phase rewrites SM_A

#pragma unroll
    for (int mt = 0; mt < 2; mt++) {
#pragma unroll
        for (int half = 0; half < 2; half++) {
            int r = row_w + mt * 16 + half * 8 + qr;
            int node = t * 128 + r;
            if (node < NN) {
                float sc = g_invs[node];
#pragma unroll
                for (int nt = 0; nt < 4; nt++) {
                    int c = col_w + nt * 8 + qc;
                    float ox = fmaxf(acc[mt][nt][2 * half] + b2s[c], 0.f) * sc;
                    float oy = fmaxf(acc[mt][nt][2 * half + 1] + b2s[c + 1], 0.f) * sc;
                    *(unsigned*)((unsigned char*)xout + ((size_t)node * LAT + c) * 2) =
                        pack_h2(ox, oy);
                }
            }
        }
    }
}

// load W+biases (cp.async, one commit group) — shared by both MMA kernels
__device__ __forceinline__ void load_weights(unsigned char* smem, unsigned sb, int step,
                                             int tid, const float* b1g, const float* b2g) {
    const unsigned char* srcW = g_wimg + (size_t)step * 2 * IMG_BYTES;
    for (int i = tid; i < 2 * IMG_BYTES / 16; i += 512)
        cpasync16(sb + SM_W1 + i * 16, srcW + i * 16);
    asm volatile("cp.async.commit_group;" ::: "memory");
    float* b1s = (float*)(smem + SM_BIAS);
    float* b2s = (float*)(smem + SM_BIAS + 512);
    if (tid < 128) b1s[tid] = b1g[tid];
    else if (tid < 256) b2s[tid - 128] = b2g[tid - 128];
}

// ---------------- mlp0: A images from g_aimg (embed output) ----------------
__global__ void __launch_bounds__(512, 2)
mlp_mma_kernel(int step, const float* __restrict__ b1g, const float* __restrict__ b2g,
               __half* __restrict__ xout) {
    extern __shared__ unsigned char smem[];
    unsigned sb = smem_u32(smem);
    int tid = threadIdx.x, wid = tid >> 5, lane = tid & 31;

    load_weights(smem, sb, step, tid, b1g, b2g);
    {
        const unsigned char* srcA = g_aimg + (size_t)blockIdx.x * IMG_BYTES;
        for (int i = tid; i < IMG_BYTES / 16; i += 512)
            cpasync16(sb + SM_A + i * 16, srcA + i * 16);
        asm volatile("cp.async.commit_group;" ::: "memory");
    }

    for (int t = blockIdx.x; t < TILES; t += NPERS) {
        asm volatile("cp.async.wait_group 0;" ::: "memory");
        __syncthreads();
        // prefetch handled at loop end; run tile
        // (A for this tile already resident)
        // --- prefetch next A during mlp? simpler: after phases (as before) ---
        // run MLP phases, but first stash next prefetch AFTER layer2 sync inside mlp_tile
        // keep the previous structure: prefetch after mlp_tile's layer2 sync is inside;
        // here do prefetch after mlp_tile completes (epi2 uses only regs + global).
        mlp_tile(smem, sb, t, tid, wid, lane, xout);
        int tn = t + NPERS;
        if (tn < TILES) {
            const unsigned char* srcA = g_aimg + (size_t)tn * IMG_BYTES;
            for (int i = tid; i < IMG_BYTES / 16; i += 512)
                cpasync16(sb + SM_A + i * 16, srcA + i * 16);
            asm volatile("cp.async.commit_group;" ::: "memory");
        }
    }
}

// ---------------- fused: gather+LN (step s-1) -> smem A -> MLP (step s) -----
__global__ void __launch_bounds__(512, 2)
fused_kernel(int step, const __half* __restrict__ xin, __half* __restrict__ xout,
             const float* __restrict__ b1g, const float* __restrict__ b2g,
             const float* __restrict__ lns, const float* __restrict__ lnb) {
    extern __shared__ unsigned char smem[];
    unsigned sb = smem_u32(smem);
    int tid = threadIdx.x, wid = tid >> 5, lane = tid & 31;

    load_weights(smem, sb, step, tid, b1g, b2g);  // overlaps first gather phase

    float4 g4 = __ldg(&((const float4*)lns)[lane]);
    float4 bb4 = __ldg(&((const float4*)lnb)[lane]);

    for (int t = blockIdx.x; t < TILES; t += NPERS) {
        // ---- gather + LN phase: warp per node, 8 nodes per warp ----
        const uint2* X = (const uint2*)xin;
#pragma unroll 1
        for (int i = 0; i < 8; i++) {
            int r = wid * 8 + i;
            int n = t * 128 + r;
            if (n >= NN) break;
            int beg = g_off[n], end = g_off[n + 1];
            float4 acc = make_float4(0.f, 0.f, 0.f, 0.f);
            int e = beg;
            for (; e + 3 < end; e += 4) {
                int s0 = g_esrc[e], s1 = g_esrc[e + 1], s2 = g_esrc[e + 2], s3 = g_esrc[e + 3];
                uint2 u0 = __ldg(&X[s0 * 32 + lane]);
                uint2 u1 = __ldg(&X[s1 * 32 + lane]);
                uint2 u2 = __ldg(&X[s2 * 32 + lane]);
                uint2 u3 = __ldg(&X[s3 * 32 + lane]);
#pragma unroll
                for (int q = 0; q < 4; q++) {
                    uint2 u = (q == 0) ? u0 : (q == 1) ? u1 : (q == 2) ? u2 : u3;
                    float2 a = __half22float2(*(__half2*)&u.x);
                    float2 b = __half22float2(*(__half2*)&u.y);
                    acc.x += a.x; acc.y += a.y; acc.z += b.x; acc.w += b.y;
                }
            }
            for (; e < end; e++) {
                int s = g_esrc[e];
                uint2 u = __ldg(&X[s * 32 + lane]);
                float2 a = __half22float2(*(__half2*)&u.x);
                float2 b = __half22float2(*(__half2*)&u.y);
                acc.x += a.x; acc.y += a.y; acc.z += b.x; acc.w += b.y;
            }
            float ir = g_invr[n];
            float4 h4 = ((const float4*)g_h)[n * 32 + lane];
            float4 v;
            v.x = h4.x + acc.x * ir;
            v.y = h4.y + acc.y * ir;
            v.z = h4.z + acc.z * ir;
            v.w = h4.w + acc.w * ir;
            float s1 = v.x + v.y + v.z + v.w;
            float s2 = v.x * v.x + v.y * v.y + v.z * v.z + v.w * v.w;
#pragma unroll
            for (int o = 16; o; o >>= 1) {
                s1 += __shfl_xor_sync(0xFFFFFFFFu, s1, o);
                s2 += __shfl_xor_sync(0xFFFFFFFFu, s2, o);
            }
            float mean = s1 * (1.f / 128.f);
            float var = s2 * (1.f / 128.f) - mean * mean;
            float rs = rsqrtf(var + 1e-6f);
            float4 o;
            o.x = (v.x - mean) * rs * g4.x + bb4.x;
            o.y = (v.y - mean) * rs * g4.y + bb4.y;
            o.z = (v.z - mean) * rs * g4.z + bb4.z;
            o.w = (v.w - mean) * rs * g4.w + bb4.w;
            ((float4*)g_h)[n * 32 + lane] = o;
            // straight into the smem A image
            *(uint2*)(smem + SM_A + ((size_t)r * PA + lane * 4) * 2) =
                make_uint2(pack_h2(o.x, o.y), pack_h2(o.z, o.w));
        }
        asm volatile("cp.async.wait_group 0;" ::: "memory");  // W ready (no-op after 1st)
        __syncthreads();

        // ---- MLP phases ----
        mlp_tile(smem, sb, t, tid, wid, lane, xout);
    }
}

// ---------------- final: gather + LN + fused decoder ----------------
__global__ void gather_ln_dec_kernel(const __half* __restrict__ xin,
                                     const float* __restrict__ lns,
                                     const float* __restrict__ lnb,
                                     const float* __restrict__ Wd,
                                     const float* __restrict__ bd,
                                     float* __restrict__ out) {
    __shared__ float Wds[LAT * NF];
    int tid = threadIdx.x;
    for (int i = tid; i < LAT * NF; i += 256) Wds[i] = Wd[i];
    __syncthreads();
    int gw = (blockIdx.x * blockDim.x + tid) >> 5;
    if (gw >= NN) return;
    int lane = tid & 31;
    int n = gw;
    int beg = g_off[n], end = g_off[n + 1];

    const uint2* X = (const uint2*)xin;
    float4 acc = make_float4(0.f, 0.f, 0.f, 0.f);
    int i = beg;
    for (; i + 3 < end; i += 4) {
        int s0 = g_esrc[i], s1 = g_esrc[i + 1], s2 = g_esrc[i + 2], s3 = g_esrc[i + 3];
        uint2 u0 = __ldg(&X[s0 * 32 + lane]);
        uint2 u1 = __ldg(&X[s1 * 32 + lane]);
        uint2 u2 = __ldg(&X[s2 * 32 + lane]);
        uint2 u3 = __ldg(&X[s3 * 32 + lane]);
#pragma unroll
        for (int q = 0; q < 4; q++) {
            uint2 u = (q == 0) ? u0 : (q == 1) ? u1 : (q == 2) ? u2 : u3;
            float2 a = __half22float2(*(__half2*)&u.x);
            float2 b = __half22float2(*(__half2*)&u.y);
            acc.x += a.x; acc.y += a.y; acc.z += b.x; acc.w += b.y;
        }
    }
    for (; i < end; i++) {
        int s = g_esrc[i];
        uint2 u = __ldg(&X[s * 32 + lane]);
        float2 a = __half22float2(*(__half2*)&u.x);
        float2 b = __half22float2(*(__half2*)&u.y);
        acc.x += a.x; acc.y += a.y; acc.z += b.x; acc.w += b.y;
    }

    float ir = g_invr[n];
    float4 h4 = ((const float4*)g_h)[n * 32 + lane];
    float4 v;
    v.x = h4.x + acc.x * ir;
    v.y = h4.y + acc.y * ir;
    v.z = h4.z + acc.z * ir;
    v.w = h4.w + acc.w * ir;

    float s1 = v.x + v.y + v.z + v.w;
    float s2 = v.x * v.x + v.y * v.y + v.z * v.z + v.w * v.w;
#pragma unroll
    for (int o = 16; o; o >>= 1) {
        s1 += __shfl_xor_sync(0xFFFFFFFFu, s1, o);
        s2 += __shfl_xor_sync(0xFFFFFFFFu, s2, o);
    }
    float mean = s1 * (1.f / 128.f);
    float var = s2 * (1.f / 128.f) - mean * mean;
    float rs = rsqrtf(var + 1e-6f);

    float4 g4 = __ldg(&((const float4*)lns)[lane]);
    float4 b4 = __ldg(&((const float4*)lnb)[lane]);
    float4 o;
    o.x = (v.x - mean) * rs * g4.x + b4.x;
    o.y = (v.y - mean) * rs * g4.y + b4.y;
    o.z = (v.z - mean) * rs * g4.z + b4.z;
    o.w = (v.w - mean) * rs * g4.w + b4.w;

    int c0 = lane * 4;
#pragma unroll
    for (int f = 0; f < NF; f++) {
        float p = o.x * Wds[(c0 + 0) * NF + f] +
                  o.y * Wds[(c0 + 1) * NF + f] +
                  o.z * Wds[(c0 + 2) * NF + f] +
                  o.w * Wds[(c0 + 3) * NF + f];
#pragma unroll
        for (int off = 16; off; off >>= 1)
            p += __shfl_xor_sync(0xFFFFFFFFu, p, off);
        if (lane == 0) out[n * NF + f] = p + bd[f];
    }
}

// ---------------- launch ----------------
extern "C" void kernel_launch(void* const* d_in, const int* in_sizes, int n_in,
                              void* d_out, int out_size) {
    const float* nodes    = (const float*)d_in[0];
    const int*   senders  = (const int*)d_in[1];
    const int*   receivers= (const int*)d_in[2];
    const float* W_embed  = (const float*)d_in[3];
    const float* b_embed  = (const float*)d_in[4];
    const float* mlp_W    = (const float*)d_in[5];
    const float* mlp_b    = (const float*)d_in[6];
    const float* ln_scale = (const float*)d_in[7];
    const float* ln_bias  = (const float*)d_in[8];
    const float* W_dec    = (const float*)d_in[9];
    const float* b_dec    = (const float*)d_in[10];
    float* out = (float*)d_out;

    cudaFuncSetAttribute((const void*)mlp_mma_kernel,
                         cudaFuncAttributeMaxDynamicSharedMemorySize, SM_TOTAL);
    cudaFuncSetAttribute((const void*)fused_kernel,
                         cudaFuncAttributeMaxDynamicSharedMemorySize, SM_TOTAL);

    __half *xA, *xB;
    cudaGetSymbolAddress((void**)&xA, g_xA);
    cudaGetSymbolAddress((void**)&xB, g_xB);

    const int NB_SCAN = (NN + 1023) / 1024;  // 49
    const float* b10 = mlp_b + 0 * LAT;
    const float* b20 = mlp_b + 1 * LAT;
    const float* b11 = mlp_b + 2 * LAT;
    const float* b21 = mlp_b + 3 * LAT;
    const float* b12 = mlp_b + 4 * LAT;
    const float* b22 = mlp_b + 5 * LAT;

    embed_deg_kernel<<<(NN + 7) / 8, 256>>>(nodes, W_embed, b_embed, mlp_W,
                                            senders, receivers);              // 1
    scan1_kernel<<<NB_SCAN, 1024>>>();                                        // 2
    scan3_kernel<<<NB_SCAN, 1024>>>();                                        // 3
    mlp_mma_kernel<<<NPERS, 512, SM_TOTAL>>>(0, b10, b20, xA);                // 4 (profiled)
    place_kernel<<<(NE + 255) / 256, 256>>>(senders, receivers);              // 5
    fused_kernel<<<NPERS, 512, SM_TOTAL>>>(1, xA, xB, b11, b21,
                                           ln_scale + 0 * LAT, ln_bias + 0 * LAT);  // 6
    fused_kernel<<<NPERS, 512, SM_TOTAL>>>(2, xB, xA, b12, b22,
                                           ln_scale + 1 * LAT, ln_bias + 1 * LAT);  // 7
    gather_ln_dec_kernel<<<(NN + 7) / 8, 256>>>(xA, ln_scale + 2 * LAT,
                                                ln_bias + 2 * LAT, W_dec, b_dec, out);  // 8
}

// round 17
// speedup vs baseline: 1.2529x; 1.2529x over previous
#include <cuda_runtime.h>
#include <cuda_bf16.h>
#include <cuda_fp16.h>

#define NN 50000
#define NE 600000
#define LAT 128
#define NF 7
#define TILES 391          // ceil(NN/128)
#define NPERS 262          // persistent mlp grid, 2 CTAs/SM
#define PA 136             // fp16 elems per image row (272B: conflict-free ldmatrix)
#define IMG_BYTES (128 * PA * 2)   // 34816

// smem layout (bytes) for mlp kernel: A + W1 + W2 (single fp16) + bias
#define SM_A    0
#define SM_W1   (SM_A + IMG_BYTES)
#define SM_W2   (SM_W1 + IMG_BYTES)
#define SM_BIAS (SM_W2 + IMG_BYTES)        // 104448
#define SM_TOTAL (SM_BIAS + 1024)          // 105472 (x2 CTAs fits)

// ---------------- scratch ----------------
__device__ __half g_h[NN * LAT];           // fp16 skip-connection state
__device__ __half g_x[NN * LAT];           // fp16 message features
__device__ float  g_degs[NN];              // zero-init; re-zeroed by place_kernel
__device__ float  g_degr[NN];
__device__ float  g_invs[NN];
__device__ float  g_invr[NN];
__device__ int    g_off[NN + 1];
__device__ int    g_cursor[NN];
__device__ int    g_esrc[NE];
__device__ int    g_bsum[64];
__device__ unsigned char g_aimg[(size_t)TILES * IMG_BYTES];   // fp16 A images
__device__ unsigned char g_wimg[6 * IMG_BYTES];               // fp16 W images

// ---------------- helpers ----------------
__device__ __forceinline__ unsigned smem_u32(const void* p) {
    unsigned a;
    asm("{ .reg .u64 t; cvta.to.shared.u64 t, %1; cvt.u32.u64 %0, t; }"
        : "=r"(a) : "l"(p));
    return a;
}
__device__ __forceinline__ void cpasync16(unsigned s, const void* g) {
    asm volatile("cp.async.cg.shared.global [%0], [%1], 16;" :: "r"(s), "l"(g));
}
__device__ __forceinline__ unsigned pack_h2(float v0, float v1) {
    __half2 h = __halves2half2(__float2half_rn(v0), __float2half_rn(v1));
    return *reinterpret_cast<unsigned*>(&h);
}
__device__ __forceinline__ void store_h_image(int n, int lane, float4 v) {
    int tile = n >> 7, r = n & 127;
    size_t off = (size_t)tile * IMG_BYTES + ((size_t)r * PA + lane * 4) * 2;
    *(uint2*)(g_aimg + off) = make_uint2(pack_h2(v.x, v.y), pack_h2(v.z, v.w));
}
__device__ __forceinline__ void store_h_fp16(int n, int lane, float4 v) {
    ((uint2*)g_h)[n * 32 + lane] = make_uint2(pack_h2(v.x, v.y), pack_h2(v.z, v.w));
}
__device__ __forceinline__ float4 load_h_fp16(int n, int lane) {
    uint2 u = ((const uint2*)g_h)[n * 32 + lane];
    float2 a = __half22float2(*(__half2*)&u.x);
    float2 b = __half22float2(*(__half2*)&u.y);
    return make_float4(a.x, a.y, b.x, b.y);
}
__device__ __forceinline__ void ldsm4(unsigned* r, unsigned addr) {
    asm volatile("ldmatrix.sync.aligned.m8n8.x4.shared.b16 {%0,%1,%2,%3}, [%4];"
                 : "=r"(r[0]), "=r"(r[1]), "=r"(r[2]), "=r"(r[3]) : "r"(addr));
}
__device__ __forceinline__ void ldsm4t(unsigned* r, unsigned addr) {
    asm volatile("ldmatrix.sync.aligned.m8n8.x4.trans.shared.b16 {%0,%1,%2,%3}, [%4];"
                 : "=r"(r[0]), "=r"(r[1]), "=r"(r[2]), "=r"(r[3]) : "r"(addr));
}
__device__ __forceinline__ void mma16816(float* d, const unsigned* a, const unsigned* b) {
    asm volatile(
        "mma.sync.aligned.m16n8k16.row.col.f32.f16.f16.f32 "
        "{%0,%1,%2,%3}, {%4,%5,%6,%7}, {%8,%9}, {%0,%1,%2,%3};"
        : "+f"(d[0]), "+f"(d[1]), "+f"(d[2]), "+f"(d[3])
        : "r"(a[0]), "r"(a[1]), "r"(a[2]), "r"(a[3]), "r"(b[0]), "r"(b[1]));
}

// ---------------- embed + weight images + degree count (degs pre-zeroed) ------
__global__ void embed_deg_kernel(const float* __restrict__ nodes,
                                 const float* __restrict__ We,
                                 const float* __restrict__ be,
                                 const float* __restrict__ mlpW,
                                 const int* __restrict__ snd,
                                 const int* __restrict__ rcv) {
    __shared__ float Wsh[NF * LAT];
    __shared__ float bsh[LAT];
    int tid = threadIdx.x;
    int gid = blockIdx.x * 256 + tid;
    if (gid < NE) {
        atomicAdd(&g_degs[snd[gid]], 1.f);
        atomicAdd(&g_degr[rcv[gid]], 1.f);
    }
    if (gid < 6 * LAT * LAT) {
        int sl = gid >> 14;
        int rem = gid & 16383;
        int k = rem >> 7;
        int j = rem & 127;
        float w = mlpW[(size_t)sl * LAT * LAT + k * LAT + j];
        size_t off = (size_t)sl * IMG_BYTES + ((size_t)k * PA + j) * 2;
        *(__half*)(g_wimg + off) = __float2half_rn(w);
    }
    for (int i = tid; i < NF * LAT; i += 256) Wsh[i] = We[i];
    if (tid < LAT) bsh[tid] = be[tid];
    __syncthreads();
    int warp = tid >> 5, lane = tid & 31;
    int n = blockIdx.x * 8 + warp;
    if (n >= NN) return;
    float t = (lane < NF) ? nodes[n * NF + lane] : 0.f;
    float f[NF];
#pragma unroll
    for (int k = 0; k < NF; k++) f[k] = __shfl_sync(0xFFFFFFFFu, t, k);
    int c0 = lane * 4;
    float4 o = make_float4(bsh[c0], bsh[c0 + 1], bsh[c0 + 2], bsh[c0 + 3]);
#pragma unroll
    for (int k = 0; k < NF; k++) {
        float4 w = *(const float4*)(Wsh + k * LAT + c0);
        o.x = fmaf(f[k], w.x, o.x);
        o.y = fmaf(f[k], w.y, o.y);
        o.z = fmaf(f[k], w.z, o.z);
        o.w = fmaf(f[k], w.w, o.w);
    }
    store_h_fp16(n, lane, o);
    store_h_image(n, lane, o);
}

// ---------------- scans ----------------
__global__ void scan1_kernel() {
    int i = blockIdx.x * 1024 + threadIdx.x;
    int v = 0;
    if (i < NN) {
        float ds = g_degs[i], dr = g_degr[i];
        g_invs[i] = rsqrtf(fmaxf(ds, 1.f));
        g_invr[i] = rsqrtf(fmaxf(dr, 1.f));
        v = (int)dr;
    }
#pragma unroll
    for (int o = 16; o; o >>= 1) v += __shfl_xor_sync(0xFFFFFFFFu, v, o);
    __shared__ int ws[32];
    int lane = threadIdx.x & 31, warp = threadIdx.x >> 5;
    if (lane == 0) ws[warp] = v;
    __syncthreads();
    if (warp == 0) {
        int t = ws[lane];
#pragma unroll
        for (int o = 16; o; o >>= 1) t += __shfl_xor_sync(0xFFFFFFFFu, t, o);
        if (lane == 0) g_bsum[blockIdx.x] = t;
    }
}

__global__ void scan3_kernel() {
    __shared__ int part[2];
    __shared__ int ws[32];
    int t = threadIdx.x;
    if (t < 64) {
        int v = (t < (int)blockIdx.x) ? g_bsum[t] : 0;
#pragma unroll
        for (int o = 16; o; o >>= 1) v += __shfl_xor_sync(0xFFFFFFFFu, v, o);
        if ((t & 31) == 0) part[t >> 5] = v;
    }
    __syncthreads();
    int base = part[0] + part[1];

    int i = blockIdx.x * 1024 + t;
    int lane = t & 31, warp = t >> 5;
    int v = (i < NN) ? (int)g_degr[i] : 0;
    int x = v;
#pragma unroll
    for (int o = 1; o < 32; o <<= 1) {
        int y = __shfl_up_sync(0xFFFFFFFFu, x, o);
        if (lane >= o) x += y;
    }
    if (lane == 31) ws[warp] = x;
    __syncthreads();
    if (warp == 0) {
        int tt = ws[lane];
        int xx = tt;
#pragma unroll
        for (int o = 1; o < 32; o <<= 1) {
            int y = __shfl_up_sync(0xFFFFFFFFu, xx, o);
            if (lane >= o) xx += y;
        }
        ws[lane] = xx - tt;
    }
    __syncthreads();
    int ex = x - v + ws[warp] + base;
    if (i < NN) { g_off[i] = ex; g_cursor[i] = ex; }
    if (i == 0) g_off[NN] = NE;
}

// place + re-zero degree arrays for next call (deterministic invariant)
__global__ void place_kernel(const int* __restrict__ snd, const int* __restrict__ rcv) {
    int e = blockIdx.x * blockDim.x + threadIdx.x;
    if (e < NN) { g_degs[e] = 0.f; g_degr[e] = 0.f; }
    if (e < NE) {
        int pos = atomicAdd(&g_cursor[rcv[e]], 1);
        g_esrc[pos] = snd[e];
    }
}

// ---------------- mma.sync fp16 (single-W) fused 2-layer MLP, 2 CTAs/SM ----------------
__device__ __forceinline__ void mma_layer(unsigned sA, unsigned sW,
                                          float acc[2][4][4],
                                          int lane, int row_w, int col_w) {
    int lr = lane & 15, lc = lane >> 4;
    int br = lane & 7, bseg = lane >> 3;
    unsigned a_base = ((row_w + lr) * PA + lc * 8) * 2;
    unsigned b_base = (((bseg & 1) * 8 + br) * PA + col_w + (bseg >> 1) * 8) * 2;

#pragma unroll
    for (int kt = 0; kt < 8; kt++) {
        unsigned a_off = a_base + kt * 32;
        unsigned b_off = b_base + kt * (16 * PA * 2);
        unsigned a[2][4], wh[2][4];
        ldsm4(a[0], sA + a_off);
        ldsm4(a[1], sA + a_off + 16 * PA * 2);
        ldsm4t(wh[0], sW + b_off);
        ldsm4t(wh[1], sW + b_off + 32);
#pragma unroll
        for (int mt = 0; mt < 2; mt++)
#pragma unroll
            for (int nt = 0; nt < 4; nt++)
                mma16816(acc[mt][nt], a[mt], &wh[nt >> 1][(nt & 1) * 2]);
    }
}

__global__ void __launch_bounds__(512, 2)
mlp_mma_kernel(int step, const float* __restrict__ b1g, const float* __restrict__ b2g) {
    extern __shared__ unsigned char smem[];
    unsigned sb = smem_u32(smem);
    int tid = threadIdx.x, wid = tid >> 5, lane = tid & 31;
    int row_w = (wid >> 2) * 32;
    int col_w = (wid & 3) * 32;
    float* b1s = (float*)(smem + SM_BIAS);
    float* b2s = (float*)(smem + SM_BIAS + 512);
    int qr = lane >> 2;
    int qc = (lane & 3) * 2;

    {
        const unsigned char* srcW = g_wimg + (size_t)step * 2 * IMG_BYTES;
        for (int i = tid; i < 2 * IMG_BYTES / 16; i += 512)
            cpasync16(sb + SM_W1 + i * 16, srcW + i * 16);
        if (tid < 128) b1s[tid] = b1g[tid];
        else if (tid < 256) b2s[tid - 128] = b2g[tid - 128];
    }
    {
        const unsigned char* srcA = g_aimg + (size_t)blockIdx.x * IMG_BYTES;
        for (int i = tid; i < IMG_BYTES / 16; i += 512)
            cpasync16(sb + SM_A + i * 16, srcA + i * 16);
        asm volatile("cp.async.commit_group;" ::: "memory");
    }

    for (int t = blockIdx.x; t < TILES; t += NPERS) {
        asm volatile("cp.async.wait_group 0;" ::: "memory");
        __syncthreads();

        float acc[2][4][4];
#pragma unroll
        for (int mt = 0; mt < 2; mt++)
#pragma unroll
            for (int nt = 0; nt < 4; nt++)
#pragma unroll
                for (int q = 0; q < 4; q++) acc[mt][nt][q] = 0.f;

        // ---- layer 1 ----
        mma_layer(sb + SM_A, sb + SM_W1, acc, lane, row_w, col_w);
        __syncthreads();

        // epilogue 1: relu + bias, fp16 back into A image
#pragma unroll
        for (int mt = 0; mt < 2; mt++)
#pragma unroll
            for (int nt = 0; nt < 4; nt++) {
                int r0 = row_w + mt * 16 + qr;
                int c = col_w + nt * 8 + qc;
                float v00 = fmaxf(acc[mt][nt][0] + b1s[c], 0.f);
                float v01 = fmaxf(acc[mt][nt][1] + b1s[c + 1], 0.f);
                float v10 = fmaxf(acc[mt][nt][2] + b1s[c], 0.f);
                float v11 = fmaxf(acc[mt][nt][3] + b1s[c + 1], 0.f);
                *(unsigned*)(smem + SM_A + (r0 * PA + c) * 2) = pack_h2(v00, v01);
                *(unsigned*)(smem + SM_A + ((r0 + 8) * PA + c) * 2) = pack_h2(v10, v11);
#pragma unroll
                for (int q = 0; q < 4; q++) acc[mt][nt][q] = 0.f;
            }
        __syncthreads();

        // ---- layer 2 ----
        mma_layer(sb + SM_A, sb + SM_W2, acc, lane, row_w, col_w);
        __syncthreads();

        // prefetch next tile's A during epilogue 2
        int tn = t + NPERS;
        if (tn < TILES) {
            const unsigned char* srcA = g_aimg + (size_t)tn * IMG_BYTES;
            for (int i = tid; i < IMG_BYTES / 16; i += 512)
                cpasync16(sb + SM_A + i * 16, srcA + i * 16);
            asm volatile("cp.async.commit_group;" ::: "memory");
        }

        // epilogue 2: relu + bias, * invs, store fp16 to g_x
#pragma unroll
        for (int mt = 0; mt < 2; mt++) {
#pragma unroll
            for (int half = 0; half < 2; half++) {
                int r = row_w + mt * 16 + half * 8 + qr;
                int node = t * 128 + r;
                if (node < NN) {
                    float sc = g_invs[node];
#pragma unroll
                    for (int nt = 0; nt < 4; nt++) {
                        int c = col_w + nt * 8 + qc;
                        float ox = fmaxf(acc[mt][nt][2 * half] + b2s[c], 0.f) * sc;
                        float oy = fmaxf(acc[mt][nt][2 * half + 1] + b2s[c + 1], 0.f) * sc;
                        *(unsigned*)((unsigned char*)g_x + ((size_t)node * LAT + c) * 2) =
                            pack_h2(ox, oy);
                    }
                }
            }
        }
    }
}

// ---------------- fused CSR-gather + skip + LN (+ optional fused decoder) ----------------
__global__ void gather_ln_kernel(const float* __restrict__ lns,
                                 const float* __restrict__ lnb, int write_img,
                                 const float* __restrict__ Wd,
                                 const float* __restrict__ bd,
                                 float* __restrict__ out) {
    __shared__ float Wds[LAT * NF];
    int tid = threadIdx.x;
    if (Wd) {
        for (int i = tid; i < LAT * NF; i += 256) Wds[i] = Wd[i];
        __syncthreads();
    }
    int gw = (blockIdx.x * blockDim.x + tid) >> 5;
    if (gw >= NN) return;
    int lane = tid & 31;
    int n = gw;
    int beg = g_off[n], end = g_off[n + 1];

    const uint2* X = (const uint2*)g_x;
    float4 acc = make_float4(0.f, 0.f, 0.f, 0.f);
    int i = beg;
    for (; i + 3 < end; i += 4) {
        int s0 = g_esrc[i], s1 = g_esrc[i + 1], s2 = g_esrc[i + 2], s3 = g_esrc[i + 3];
        uint2 u0 = __ldg(&X[s0 * 32 + lane]);
        uint2 u1 = __ldg(&X[s1 * 32 + lane]);
        uint2 u2 = __ldg(&X[s2 * 32 + lane]);
        uint2 u3 = __ldg(&X[s3 * 32 + lane]);
#pragma unroll
        for (int q = 0; q < 4; q++) {
            uint2 u = (q == 0) ? u0 : (q == 1) ? u1 : (q == 2) ? u2 : u3;
            float2 a = __half22float2(*(__half2*)&u.x);
            float2 b = __half22float2(*(__half2*)&u.y);
            acc.x += a.x; acc.y += a.y; acc.z += b.x; acc.w += b.y;
        }
    }
    for (; i < end; i++) {
        int s = g_esrc[i];
        uint2 u = __ldg(&X[s * 32 + lane]);
        float2 a = __half22float2(*(__half2*)&u.x);
        float2 b = __half22float2(*(__half2*)&u.y);
        acc.x += a.x; acc.y += a.y; acc.z += b.x; acc.w += b.y;
    }

    float ir = g_invr[n];
    float4 h4 = load_h_fp16(n, lane);
    float4 v;
    v.x = h4.x + acc.x * ir;
    v.y = h4.y + acc.y * ir;
    v.z = h4.z + acc.z * ir;
    v.w = h4.w + acc.w * ir;

    float s1 = v.x + v.y + v.z + v.w;
    float s2 = v.x * v.x + v.y * v.y + v.z * v.z + v.w * v.w;
#pragma unroll
    for (int o = 16; o; o >>= 1) {
        s1 += __shfl_xor_sync(0xFFFFFFFFu, s1, o);
        s2 += __shfl_xor_sync(0xFFFFFFFFu, s2, o);
    }
    float mean = s1 * (1.f / 128.f);
    float var = s2 * (1.f / 128.f) - mean * mean;
    float rs = rsqrtf(var + 1e-6f);

    float4 g4 = __ldg(&((const float4*)lns)[lane]);
    float4 b4 = __ldg(&((const float4*)lnb)[lane]);
    float4 o;
    o.x = (v.x - mean) * rs * g4.x + b4.x;
    o.y = (v.y - mean) * rs * g4.y + b4.y;
    o.z = (v.z - mean) * rs * g4.z + b4.z;
    o.w = (v.w - mean) * rs * g4.w + b4.w;

    if (Wd) {
        int c0 = lane * 4;
#pragma unroll
        for (int f = 0; f < NF; f++) {
            float p = o.x * Wds[(c0 + 0) * NF + f] +
                      o.y * Wds[(c0 + 1) * NF + f] +
                      o.z * Wds[(c0 + 2) * NF + f] +
                      o.w * Wds[(c0 + 3) * NF + f];
#pragma unroll
            for (int off = 16; off; off >>= 1)
                p += __shfl_xor_sync(0xFFFFFFFFu, p, off);
            if (lane == 0) out[n * NF + f] = p + bd[f];
        }
    } else {
        store_h_fp16(n, lane, o);
        if (write_img) store_h_image(n, lane, o);
    }
}

// ---------------- launch ----------------
extern "C" void kernel_launch(void* const* d_in, const int* in_sizes, int n_in,
                              void* d_out, int out_size) {
    const float* nodes    = (const float*)d_in[0];
    const int*   senders  = (const int*)d_in[1];
    const int*   receivers= (const int*)d_in[2];
    const float* W_embed  = (const float*)d_in[3];
    const float* b_embed  = (const float*)d_in[4];
    const float* mlp_W    = (const float*)d_in[5];
    const float* mlp_b    = (const float*)d_in[6];
    const float* ln_scale = (const float*)d_in[7];
    const float* ln_bias  = (const float*)d_in[8];
    const float* W_dec    = (const float*)d_in[9];
    const float* b_dec    = (const float*)d_in[10];
    float* out = (float*)d_out;

    cudaFuncSetAttribute((const void*)mlp_mma_kernel,
                         cudaFuncAttributeMaxDynamicSharedMemorySize, SM_TOTAL);

    const int NB_SCAN = (NN + 1023) / 1024;  // 49

    // order: mlp step0 is the 4th launch (ncu capture slot)
    embed_deg_kernel<<<(NN + 7) / 8, 256>>>(nodes, W_embed, b_embed, mlp_W,
                                            senders, receivers);              // 1
    scan1_kernel<<<NB_SCAN, 1024>>>();                                        // 2
    scan3_kernel<<<NB_SCAN, 1024>>>();                                        // 3

    for (int s = 0; s < 3; s++) {
        const float* b1 = mlp_b + (size_t)(s * 2 + 0) * LAT;
        const float* b2 = mlp_b + (size_t)(s * 2 + 1) * LAT;
        mlp_mma_kernel<<<NPERS, 512, SM_TOTAL>>>(s, b1, b2);                  // 4 on s=0
        if (s == 0)
            place_kernel<<<(NE + 255) / 256, 256>>>(senders, receivers);      // 5
        if (s < 2) {
            gather_ln_kernel<<<(NN + 7) / 8, 256>>>(
                ln_scale + s * LAT, ln_bias + s * LAT, 1, nullptr, nullptr, nullptr);
        } else {
            gather_ln_kernel<<<(NN + 7) / 8, 256>>>(
                ln_scale + s * LAT, ln_bias + s * LAT, 0, W_dec, b_dec, out);
        }
    }
}